// round 6
// baseline (speedup 1.0000x reference)
#include <cuda_runtime.h>
#include <math.h>
#include <stdint.h>

// Problem constants (fixed by reference: N=32, C=256, H=W=32)
#define NB 32
#define CDIM 256
#define HW 1024
#define WD 32

// ---------------- device scratch (no allocations allowed) ----------------
__device__ double g_sum[64];                 // masked cos sum per (loss, n)
__device__ double g_cnt[64];                 // mask count per (loss, n)
__device__ float  g_norms[4][NB * HW];       // ||.|| for p1,p2,z1,z2
__device__ float  g_cx[2][NB * HW];          // centers x for coord_1, coord_2
__device__ float  g_cy[2][NB * HW];          // centers y
__device__ float  g_maxdiag[NB];             // max(diag1, diag2) per n
// TF32-quantized, transposed copies: [t][n][p][k_perm], row = 256 floats.
// Within each 16-k block, element k_local stored at (k_local%4)*4 + k_local/4.
__device__ float  g_tf32[4ull * NB * HW * CDIM];   // 134 MB

// Round fp32 -> TF32 (10-bit mantissa), same conversion cuBLAS/CUTLASS use.
__device__ __forceinline__ float tf32r(float x) {
    uint32_t u;
    asm("cvt.rna.tf32.f32 %0, %1;" : "=r"(u) : "f"(x));
    return __uint_as_float(u);
}

// m16n8k8 TF32 MMA, fp32 accumulate
__device__ __forceinline__ void mma_tf32(float* d,
                                         float a0, float a1, float a2, float a3,
                                         float b0, float b1) {
    asm volatile(
        "mma.sync.aligned.m16n8k8.row.col.f32.tf32.tf32.f32 "
        "{%0,%1,%2,%3}, {%4,%5,%6,%7}, {%8,%9}, {%0,%1,%2,%3};\n"
        : "+f"(d[0]), "+f"(d[1]), "+f"(d[2]), "+f"(d[3])
        : "r"(__float_as_uint(a0)), "r"(__float_as_uint(a1)),
          "r"(__float_as_uint(a2)), "r"(__float_as_uint(a3)),
          "r"(__float_as_uint(b0)), "r"(__float_as_uint(b1)));
}

#define CP_ASYNC16(dst32, srcp) \
    asm volatile("cp.async.cg.shared.global [%0], [%1], 16;\n" :: "r"(dst32), "l"(srcp))
#define CP_COMMIT() asm volatile("cp.async.commit_group;\n")
#define CP_WAIT(n)  asm volatile("cp.async.wait_group %0;\n" :: "n"(n))

// ---------------- kernels ----------------
__global__ void zero_kernel() {
    int i = threadIdx.x;
    if (i < 64) { g_sum[i] = 0.0; g_cnt[i] = 0.0; }
}

// grid (NB, 4), block 1024: norms on ORIGINAL fp32 data (reference does not
// quantize the norm path).
__global__ void norms_kernel(const float* __restrict__ p1, const float* __restrict__ p2,
                             const float* __restrict__ z1, const float* __restrict__ z2) {
    int n = blockIdx.x;
    int t = blockIdx.y;
    int p = threadIdx.x;
    const float* src = (t == 0) ? p1 : (t == 1) ? p2 : (t == 2) ? z1 : z2;
    const float* base = src + (size_t)n * CDIM * HW + p;
    float acc = 0.f;
#pragma unroll 8
    for (int c = 0; c < CDIM; ++c) {
        float v = base[(size_t)c * HW];
        acc += v * v;
    }
    g_norms[t][n * HW + p] = sqrtf(acc);
}

// grid (NB), block 1024: centers + max_diag, exact reference arithmetic.
__global__ void centers_kernel(const float* __restrict__ c1, const float* __restrict__ c2) {
    int n = blockIdx.x;
    int p = threadIdx.x;
    float a0 = c1[n * 4 + 0], a1 = c1[n * 4 + 1], a2 = c1[n * 4 + 2], a3 = c1[n * 4 + 3];
    float b0 = c2[n * 4 + 0], b1 = c2[n * 4 + 1], b2 = c2[n * 4 + 2], b3 = c2[n * 4 + 3];
    float bw1 = __fdiv_rn(__fsub_rn(a2, a0), 32.0f), bh1 = __fdiv_rn(__fsub_rn(a3, a1), 32.0f);
    float bw2 = __fdiv_rn(__fsub_rn(b2, b0), 32.0f), bh2 = __fdiv_rn(__fsub_rn(b3, b1), 32.0f);
    float x = (float)(p % WD);
    float y = (float)(p / WD);
    g_cx[0][n * HW + p] = __fadd_rn(__fmul_rn(__fadd_rn(x, 0.5f), bw1), a0);
    g_cy[0][n * HW + p] = __fadd_rn(__fmul_rn(__fadd_rn(y, 0.5f), bh1), a1);
    g_cx[1][n * HW + p] = __fadd_rn(__fmul_rn(__fadd_rn(x, 0.5f), bw2), b0);
    g_cy[1][n * HW + p] = __fadd_rn(__fmul_rn(__fadd_rn(y, 0.5f), bh2), b1);
    if (p == 0) {
        float d1 = __fsqrt_rn(__fadd_rn(__fmul_rn(bw1, bw1), __fmul_rn(bh1, bh1)));
        float d2 = __fsqrt_rn(__fadd_rn(__fmul_rn(bw2, bw2), __fmul_rn(bh2, bh2)));
        g_maxdiag[n] = fmaxf(d1, d2);
    }
}

// Transpose + TF32-quantize: in [n][c][p] -> g_tf32 [t][n][p][c_perm].
// grid (256 = 32 ptiles * 8 ctiles, NB, 4), block 256. 32x32 smem tile.
__global__ __launch_bounds__(256) void transq_kernel(
    const float* __restrict__ p1, const float* __restrict__ p2,
    const float* __restrict__ z1, const float* __restrict__ z2) {
    int t = blockIdx.z;
    int n = blockIdx.y;
    int pt = blockIdx.x & 31;
    int ct = blockIdx.x >> 5;
    int p0 = pt * 32, c0 = ct * 32;
    const float* src = (t == 0) ? p1 : (t == 1) ? p2 : (t == 2) ? z1 : z2;
    src += (size_t)n * CDIM * HW;

    __shared__ float s[32][33];
    int tid = threadIdx.x;
    int rc = tid >> 5;        // 0..7
    int rp = tid & 31;        // 0..31
#pragma unroll
    for (int j = 0; j < 4; ++j) {
        int c = rc + j * 8;
        s[c][rp] = src[(size_t)(c0 + c) * HW + p0 + rp];
    }
    __syncthreads();

    float* dst = g_tf32 + ((size_t)(t * NB + n) * HW) * CDIM;
    int cw = tid & 31;        // column (c_sub) for write
    int cl = cw & 15;
    int cperm = (cw & 16) + ((cl & 3) << 2) + (cl >> 2);
#pragma unroll
    for (int j = 0; j < 4; ++j) {
        int p = (tid >> 5) + j * 8;
        dst[(size_t)(p0 + p) * CDIM + c0 + cperm] = tf32r(s[cw][p]);
    }
}

// Fused TF32 tensor-core GEMM + cosine + mask + masked-mean reduction.
// Operands come pre-quantized & pre-permuted from g_tf32 ([p][k_perm] rows).
// 128x128 tile, BK=16, cp.async double buffer, 8 warps (2x4), warp 64x32.
#define BM 128
#define BN 128
#define BK 16

__global__ __launch_bounds__(256) void gemm_loss_kernel() {
    int z = blockIdx.z;          // 0..63 : (loss, n)
    int n = z & 31;
    int which = z >> 5;          // 0 -> (p1, z2), 1 -> (p2, z1)

    const float *Q, *K, *qn, *kn, *qcx, *qcy, *kcx, *kcy;
    if (which == 0) {
        Q = g_tf32 + ((size_t)(0 * NB + n) * HW) * CDIM;
        K = g_tf32 + ((size_t)(3 * NB + n) * HW) * CDIM;
        qn = &g_norms[0][n * HW]; kn = &g_norms[3][n * HW];
        qcx = &g_cx[0][n * HW]; qcy = &g_cy[0][n * HW];
        kcx = &g_cx[1][n * HW]; kcy = &g_cy[1][n * HW];
    } else {
        Q = g_tf32 + ((size_t)(1 * NB + n) * HW) * CDIM;
        K = g_tf32 + ((size_t)(2 * NB + n) * HW) * CDIM;
        qn = &g_norms[1][n * HW]; kn = &g_norms[2][n * HW];
        qcx = &g_cx[1][n * HW]; qcy = &g_cy[1][n * HW];
        kcx = &g_cx[0][n * HW]; kcy = &g_cy[0][n * HW];
    }
    float maxdiag = g_maxdiag[n];

    __shared__ float As2[2][BM][BK];
    __shared__ float Bs2[2][BN][BK];
    __shared__ float redS[256];
    __shared__ float redC[256];

    int tid  = threadIdx.x;
    int lane = tid & 31;
    int warp = tid >> 5;          // 0..7
    int gid  = lane >> 2;         // 0..7
    int tig  = lane & 3;          // 0..3
    int warpM = warp >> 2;        // 0..1
    int warpN = warp & 3;         // 0..3
    int pBase = blockIdx.x * BM;
    int qBase = blockIdx.y * BN;

    // cp.async mapping: thread covers (row r, 16B chunk o) pairs
    int cr = tid >> 2;            // 0..63
    int co = (tid & 3) * 4;       // 0,4,8,12

    uint32_t sA = (uint32_t)__cvta_generic_to_shared(&As2[0][0][0]);
    uint32_t sB = (uint32_t)__cvta_generic_to_shared(&Bs2[0][0][0]);
    const uint32_t bufBytes = BM * BK * 4;   // 8KB per buffer

    float d[4][4][4];
#pragma unroll
    for (int mt = 0; mt < 4; ++mt)
#pragma unroll
        for (int nt = 0; nt < 4; ++nt)
#pragma unroll
            for (int r = 0; r < 4; ++r) d[mt][nt][r] = 0.f;

    // preload tile 0
    {
        uint32_t dA = sA + (uint32_t)((cr * BK + co) * 4);
        uint32_t dB = sB + (uint32_t)((cr * BK + co) * 4);
        CP_ASYNC16(dA,                      Q + (size_t)(pBase + cr) * CDIM + co);
        CP_ASYNC16(dA + 64u * BK * 4u,      Q + (size_t)(pBase + cr + 64) * CDIM + co);
        CP_ASYNC16(dB,                      K + (size_t)(qBase + cr) * CDIM + co);
        CP_ASYNC16(dB + 64u * BK * 4u,      K + (size_t)(qBase + cr + 64) * CDIM + co);
        CP_COMMIT();
    }

#pragma unroll 1
    for (int kt = 0; kt < CDIM / BK; ++kt) {
        int cur = kt & 1;
        if (kt + 1 < CDIM / BK) {
            int nxt = cur ^ 1;
            int kc = (kt + 1) * BK + co;
            uint32_t dA = sA + nxt * bufBytes + (uint32_t)((cr * BK + co) * 4);
            uint32_t dB = sB + nxt * bufBytes + (uint32_t)((cr * BK + co) * 4);
            CP_ASYNC16(dA,                  Q + (size_t)(pBase + cr) * CDIM + kc);
            CP_ASYNC16(dA + 64u * BK * 4u,  Q + (size_t)(pBase + cr + 64) * CDIM + kc);
            CP_ASYNC16(dB,                  K + (size_t)(qBase + cr) * CDIM + kc);
            CP_ASYNC16(dB + 64u * BK * 4u,  K + (size_t)(qBase + cr + 64) * CDIM + kc);
            CP_COMMIT();
            CP_WAIT(1);
        } else {
            CP_WAIT(0);
        }
        __syncthreads();

        // B fragments: one float4 per nt covers both k8 steps
        float4 wb[4];
#pragma unroll
        for (int nt = 0; nt < 4; ++nt)
            wb[nt] = *(const float4*)&Bs2[cur][warpN * 32 + nt * 8 + gid][tig * 4];
#pragma unroll
        for (int mt = 0; mt < 4; ++mt) {
            int pm = warpM * 64 + mt * 16 + gid;
            float4 va = *(const float4*)&As2[cur][pm][tig * 4];
            float4 vb = *(const float4*)&As2[cur][pm + 8][tig * 4];
            // k8 step 0: k = {tig, tig+4}
#pragma unroll
            for (int nt = 0; nt < 4; ++nt)
                mma_tf32(d[mt][nt], va.x, vb.x, va.y, vb.y, wb[nt].x, wb[nt].y);
            // k8 step 1: k = {8+tig, 12+tig}
#pragma unroll
            for (int nt = 0; nt < 4; ++nt)
                mma_tf32(d[mt][nt], va.z, vb.z, va.w, vb.w, wb[nt].z, wb[nt].w);
        }
        __syncthreads();
    }

    // Epilogue: cosine sim + geometric mask on MMA D-fragment layout.
    float qnv[4][2], qxv[4][2], qyv[4][2];
#pragma unroll
    for (int mt = 0; mt < 4; ++mt)
#pragma unroll
        for (int i2 = 0; i2 < 2; ++i2) {
            int p = pBase + warpM * 64 + mt * 16 + gid + i2 * 8;
            qnv[mt][i2] = qn[p]; qxv[mt][i2] = qcx[p]; qyv[mt][i2] = qcy[p];
        }
    float knv[4][2], kxv[4][2], kyv[4][2];
#pragma unroll
    for (int nt = 0; nt < 4; ++nt)
#pragma unroll
        for (int j2 = 0; j2 < 2; ++j2) {
            int q = qBase + warpN * 32 + nt * 8 + 2 * tig + j2;
            knv[nt][j2] = kn[q]; kxv[nt][j2] = kcx[q]; kyv[nt][j2] = kcy[q];
        }

    float lsum = 0.f, lcnt = 0.f;
#pragma unroll
    for (int mt = 0; mt < 4; ++mt) {
#pragma unroll
        for (int nt = 0; nt < 4; ++nt) {
#pragma unroll
            for (int r = 0; r < 4; ++r) {
                int i2 = r >> 1, j2 = r & 1;
                float denom = fmaxf(__fmul_rn(qnv[mt][i2], knv[nt][j2]), 1e-8f);
                float cosv = __fdiv_rn(d[mt][nt][r], denom);
                float dx = __fsub_rn(qxv[mt][i2], kxv[nt][j2]);
                float dy = __fsub_rn(qyv[mt][i2], kyv[nt][j2]);
                float d2v = __fadd_rn(__fmul_rn(dx, dx), __fmul_rn(dy, dy));
                float dist = __fdiv_rn(__fsqrt_rn(d2v), maxdiag);
                if (dist < 16.0f) {   // pos_ratio * H = 0.5 * 32
                    lsum += cosv;
                    lcnt += 1.0f;
                }
            }
        }
    }

    redS[tid] = lsum;
    redC[tid] = lcnt;
    __syncthreads();
#pragma unroll
    for (int s = 128; s > 0; s >>= 1) {
        if (tid < s) { redS[tid] += redS[tid + s]; redC[tid] += redC[tid + s]; }
        __syncthreads();
    }
    if (tid == 0) {
        atomicAdd(&g_sum[z], (double)redS[0]);
        atomicAdd(&g_cnt[z], (double)redC[0]);
    }
}

__global__ void final_kernel(float* __restrict__ out) {
    double l1 = 0.0, l2 = 0.0;
    for (int n = 0; n < 32; ++n) {
        l1 += g_sum[n]      / (g_cnt[n]      + 1e-6);
        l2 += g_sum[32 + n] / (g_cnt[32 + n] + 1e-6);
    }
    out[0] = (float)(-((l1 / 32.0) + (l2 / 32.0)) * 0.5);
}

// ---------------- launch ----------------
extern "C" void kernel_launch(void* const* d_in, const int* in_sizes, int n_in,
                              void* d_out, int out_size) {
    const float* p1 = (const float*)d_in[0];
    const float* p2 = (const float*)d_in[1];
    const float* z1 = (const float*)d_in[2];
    const float* z2 = (const float*)d_in[3];
    const float* c1 = (const float*)d_in[4];
    const float* c2 = (const float*)d_in[5];
    float* out = (float*)d_out;

    zero_kernel<<<1, 64>>>();
    norms_kernel<<<dim3(NB, 4), 1024>>>(p1, p2, z1, z2);
    centers_kernel<<<NB, 1024>>>(c1, c2);
    transq_kernel<<<dim3(256, NB, 4), 256>>>(p1, p2, z1, z2);
    gemm_loss_kernel<<<dim3(8, 8, 64), 256>>>();
    final_kernel<<<1, 1>>>(out);
}

// round 9
// speedup vs baseline: 1.0410x; 1.0410x over previous
#include <cuda_runtime.h>
#include <math.h>
#include <stdint.h>

// Problem constants (fixed by reference: N=32, C=256, H=W=32)
#define NB 32
#define CDIM 256
#define HW 1024
#define WD 32

// ---------------- device scratch (no allocations allowed) ----------------
__device__ double g_sum[64];                 // masked cos sum per (loss, n)
__device__ double g_cnt[64];                 // mask count per (loss, n)
__device__ float  g_norms[4][NB * HW];       // ||.|| for p1,p2,z1,z2
__device__ float  g_cx[2][NB * HW];          // centers x for coord_1, coord_2
__device__ float  g_cy[2][NB * HW];          // centers y
__device__ float  g_maxdiag[NB];             // max(diag1, diag2) per n
// TF32-quantized, transposed copies: [t][n][p][k], row = 256 floats (1KB).
__device__ float  g_tf32[4ull * NB * HW * CDIM];   // 134 MB

// Round fp32 -> TF32 (10-bit mantissa), same conversion cuBLAS/CUTLASS use.
__device__ __forceinline__ float tf32r(float x) {
    uint32_t u;
    asm("cvt.rna.tf32.f32 %0, %1;" : "=r"(u) : "f"(x));
    return __uint_as_float(u);
}

// m16n8k8 TF32 MMA, fp32 accumulate
__device__ __forceinline__ void mma_tf32(float* d,
                                         float a0, float a1, float a2, float a3,
                                         float b0, float b1) {
    asm volatile(
        "mma.sync.aligned.m16n8k8.row.col.f32.tf32.tf32.f32 "
        "{%0,%1,%2,%3}, {%4,%5,%6,%7}, {%8,%9}, {%0,%1,%2,%3};\n"
        : "+f"(d[0]), "+f"(d[1]), "+f"(d[2]), "+f"(d[3])
        : "r"(__float_as_uint(a0)), "r"(__float_as_uint(a1)),
          "r"(__float_as_uint(a2)), "r"(__float_as_uint(a3)),
          "r"(__float_as_uint(b0)), "r"(__float_as_uint(b1)));
}

#define CP_ASYNC16(dst32, srcp) \
    asm volatile("cp.async.cg.shared.global [%0], [%1], 16;\n" :: "r"(dst32), "l"(srcp))
#define CP_COMMIT() asm volatile("cp.async.commit_group;\n")
#define CP_WAIT(n)  asm volatile("cp.async.wait_group %0;\n" :: "n"(n))

// ---------------- kernels ----------------
__global__ void zero_kernel() {
    int i = threadIdx.x;
    if (i < 64) { g_sum[i] = 0.0; g_cnt[i] = 0.0; }
}

// grid (NB), block 1024: centers + max_diag, exact reference arithmetic.
__global__ void centers_kernel(const float* __restrict__ c1, const float* __restrict__ c2) {
    int n = blockIdx.x;
    int p = threadIdx.x;
    float a0 = c1[n * 4 + 0], a1 = c1[n * 4 + 1], a2 = c1[n * 4 + 2], a3 = c1[n * 4 + 3];
    float b0 = c2[n * 4 + 0], b1 = c2[n * 4 + 1], b2 = c2[n * 4 + 2], b3 = c2[n * 4 + 3];
    float bw1 = __fdiv_rn(__fsub_rn(a2, a0), 32.0f), bh1 = __fdiv_rn(__fsub_rn(a3, a1), 32.0f);
    float bw2 = __fdiv_rn(__fsub_rn(b2, b0), 32.0f), bh2 = __fdiv_rn(__fsub_rn(b3, b1), 32.0f);
    float x = (float)(p % WD);
    float y = (float)(p / WD);
    g_cx[0][n * HW + p] = __fadd_rn(__fmul_rn(__fadd_rn(x, 0.5f), bw1), a0);
    g_cy[0][n * HW + p] = __fadd_rn(__fmul_rn(__fadd_rn(y, 0.5f), bh1), a1);
    g_cx[1][n * HW + p] = __fadd_rn(__fmul_rn(__fadd_rn(x, 0.5f), bw2), b0);
    g_cy[1][n * HW + p] = __fadd_rn(__fmul_rn(__fadd_rn(y, 0.5f), bh2), b1);
    if (p == 0) {
        float d1 = __fsqrt_rn(__fadd_rn(__fmul_rn(bw1, bw1), __fmul_rn(bh1, bh1)));
        float d2 = __fsqrt_rn(__fadd_rn(__fmul_rn(bw2, bw2), __fmul_rn(bh2, bh2)));
        g_maxdiag[n] = fmaxf(d1, d2);
    }
}

// Fused prep: transpose [c][p] -> [p][c], TF32-quantize into g_tf32, AND
// accumulate the exact-fp32 column norms in the same single read pass.
// grid (32 ptiles, NB, 4), block 256. 32x32 smem tile.
__global__ __launch_bounds__(256) void prep_kernel(
    const float* __restrict__ p1, const float* __restrict__ p2,
    const float* __restrict__ z1, const float* __restrict__ z2) {
    int t = blockIdx.z;
    int n = blockIdx.y;
    int p0 = blockIdx.x * 32;
    const float* src = (t == 0) ? p1 : (t == 1) ? p2 : (t == 2) ? z1 : z2;
    src += (size_t)n * CDIM * HW;
    float* dst = g_tf32 + ((size_t)(t * NB + n) * HW) * CDIM;

    __shared__ float s[32][33];
    __shared__ float part[8][32];
    int tid = threadIdx.x;
    int rc = tid >> 5;        // 0..7
    int rp = tid & 31;        // 0..31
    float acc = 0.f;

#pragma unroll 1
    for (int ct = 0; ct < 8; ++ct) {
        int c0 = ct * 32;
#pragma unroll
        for (int j = 0; j < 4; ++j) {
            int c = rc + j * 8;
            s[c][rp] = src[(size_t)(c0 + c) * HW + p0 + rp];
        }
        __syncthreads();
        // norms: group rc handles c in {4rc..4rc+3}, column rp
#pragma unroll
        for (int i = 0; i < 4; ++i) {
            float v = s[rc * 4 + i][rp];
            acc += v * v;
        }
        // transposed quantized write: lane = c within tile
#pragma unroll
        for (int j = 0; j < 4; ++j) {
            int p = rc + j * 8;
            dst[(size_t)(p0 + p) * CDIM + c0 + rp] = tf32r(s[rp][p]);
        }
        __syncthreads();
    }
    part[rc][rp] = acc;
    __syncthreads();
    if (tid < 32) {
        float n2 = 0.f;
#pragma unroll
        for (int g = 0; g < 8; ++g) n2 += part[g][tid];
        g_norms[t][n * HW + p0 + tid] = sqrtf(n2);
    }
}

// Fused TF32 tensor-core GEMM + cosine + mask + masked-mean reduction.
// 128(p) x 64(q) tile, BK=16, 3-stage cp.async ring, ONE barrier per stage:
//   wait(own groups) -> __syncthreads -> issue stage kt+2 -> compute stage kt
// The barrier makes all threads' stage-kt copies visible AND fences iter kt-1
// reads of buffer (kt+2)%3 from this iter's writes into it.
#define BM 128
#define BNQ 64
#define BK 16
#define NSTG 3
#define NT (CDIM / BK)    // 16 k-tiles

__global__ __launch_bounds__(256, 3) void gemm_loss_kernel() {
    int z = blockIdx.z;          // 0..63 : (loss, n)
    int n = z & 31;
    int which = z >> 5;          // 0 -> (p1, z2), 1 -> (p2, z1)

    const float *Q, *K, *qn, *kn, *qcx, *qcy, *kcx, *kcy;
    if (which == 0) {
        Q = g_tf32 + ((size_t)(0 * NB + n) * HW) * CDIM;
        K = g_tf32 + ((size_t)(3 * NB + n) * HW) * CDIM;
        qn = &g_norms[0][n * HW]; kn = &g_norms[3][n * HW];
        qcx = &g_cx[0][n * HW]; qcy = &g_cy[0][n * HW];
        kcx = &g_cx[1][n * HW]; kcy = &g_cy[1][n * HW];
    } else {
        Q = g_tf32 + ((size_t)(1 * NB + n) * HW) * CDIM;
        K = g_tf32 + ((size_t)(2 * NB + n) * HW) * CDIM;
        qn = &g_norms[1][n * HW]; kn = &g_norms[2][n * HW];
        qcx = &g_cx[1][n * HW]; qcy = &g_cy[1][n * HW];
        kcx = &g_cx[0][n * HW]; kcy = &g_cy[0][n * HW];
    }
    float maxdiag = g_maxdiag[n];

    __shared__ float As3[NSTG][BM][BK];     // 24 KB
    __shared__ float Bs3[NSTG][BNQ][BK];    // 12 KB
    __shared__ float redS[256];
    __shared__ float redC[256];

    int tid  = threadIdx.x;
    int lane = tid & 31;
    int warp = tid >> 5;          // 0..7
    int gid  = lane >> 2;         // 0..7
    int tig  = lane & 3;          // 0..3
    int warpM = warp >> 1;        // 0..3 -> 32-row band
    int warpN = warp & 1;         // 0..1 -> 32-col band
    int pBase = blockIdx.x * BM;
    int qBase = blockIdx.y * BNQ;

    // cp.async mapping: cr = row (0..63), co = float offset of 16B chunk
    int cr = tid >> 2;            // 0..63
    int co = (tid & 3) * 4;       // 0,4,8,12

    uint32_t sA = (uint32_t)__cvta_generic_to_shared(&As3[0][0][0]);
    uint32_t sB = (uint32_t)__cvta_generic_to_shared(&Bs3[0][0][0]);
    const uint32_t aBuf = BM * BK * 4;    // 8 KB
    const uint32_t bBuf = BNQ * BK * 4;   // 4 KB
    uint32_t thOff = (uint32_t)((cr * BK + co) * 4);

    float d[2][4][4];
#pragma unroll
    for (int mt = 0; mt < 2; ++mt)
#pragma unroll
        for (int nt = 0; nt < 4; ++nt)
#pragma unroll
            for (int r = 0; r < 4; ++r) d[mt][nt][r] = 0.f;

    // prologue: issue stages 0 and 1 as separate groups
#pragma unroll
    for (int st = 0; st < 2; ++st) {
        int kc = st * BK + co;
        CP_ASYNC16(sA + st * aBuf + thOff,                 Q + (size_t)(pBase + cr) * CDIM + kc);
        CP_ASYNC16(sA + st * aBuf + thOff + 64u * BK * 4u, Q + (size_t)(pBase + cr + 64) * CDIM + kc);
        CP_ASYNC16(sB + st * bBuf + thOff,                 K + (size_t)(qBase + cr) * CDIM + kc);
        CP_COMMIT();
    }

    int cur = 0;        // kt % 3
    int nxt2 = 2;       // (kt+2) % 3
#pragma unroll 1
    for (int kt = 0; kt < NT; ++kt) {
        if (kt < NT - 1) { CP_WAIT(1); } else { CP_WAIT(0); }
        __syncthreads();   // stage kt visible to all; fences reuse of buffer nxt2
        if (kt + 2 < NT) {
            int kc = (kt + 2) * BK + co;
            CP_ASYNC16(sA + nxt2 * aBuf + thOff,                 Q + (size_t)(pBase + cr) * CDIM + kc);
            CP_ASYNC16(sA + nxt2 * aBuf + thOff + 64u * BK * 4u, Q + (size_t)(pBase + cr + 64) * CDIM + kc);
            CP_ASYNC16(sB + nxt2 * bBuf + thOff,                 K + (size_t)(qBase + cr) * CDIM + kc);
            CP_COMMIT();
        }
        // B fragments: one float4 per nt covers both k8 steps
        float4 wb[4];
#pragma unroll
        for (int nt = 0; nt < 4; ++nt)
            wb[nt] = *(const float4*)&Bs3[cur][warpN * 32 + nt * 8 + gid][tig * 4];
#pragma unroll
        for (int mt = 0; mt < 2; ++mt) {
            int pm = warpM * 32 + mt * 16 + gid;
            float4 va = *(const float4*)&As3[cur][pm][tig * 4];
            float4 vb = *(const float4*)&As3[cur][pm + 8][tig * 4];
#pragma unroll
            for (int nt = 0; nt < 4; ++nt)
                mma_tf32(d[mt][nt], va.x, vb.x, va.y, vb.y, wb[nt].x, wb[nt].y);
#pragma unroll
            for (int nt = 0; nt < 4; ++nt)
                mma_tf32(d[mt][nt], va.z, vb.z, va.w, vb.w, wb[nt].z, wb[nt].w);
        }
        cur = (cur == 2) ? 0 : cur + 1;
        nxt2 = (nxt2 == 2) ? 0 : nxt2 + 1;
    }

    // Epilogue: cosine sim + geometric mask on MMA D-fragment layout.
    float qnv[2][2], qxv[2][2], qyv[2][2];
#pragma unroll
    for (int mt = 0; mt < 2; ++mt)
#pragma unroll
        for (int i2 = 0; i2 < 2; ++i2) {
            int p = pBase + warpM * 32 + mt * 16 + gid + i2 * 8;
            qnv[mt][i2] = qn[p]; qxv[mt][i2] = qcx[p]; qyv[mt][i2] = qcy[p];
        }
    float knv[4][2], kxv[4][2], kyv[4][2];
#pragma unroll
    for (int nt = 0; nt < 4; ++nt)
#pragma unroll
        for (int j2 = 0; j2 < 2; ++j2) {
            int q = qBase + warpN * 32 + nt * 8 + 2 * tig + j2;
            knv[nt][j2] = kn[q]; kxv[nt][j2] = kcx[q]; kyv[nt][j2] = kcy[q];
        }

    float lsum = 0.f, lcnt = 0.f;
#pragma unroll
    for (int mt = 0; mt < 2; ++mt) {
#pragma unroll
        for (int nt = 0; nt < 4; ++nt) {
#pragma unroll
            for (int r = 0; r < 4; ++r) {
                int i2 = r >> 1, j2 = r & 1;
                float denom = fmaxf(__fmul_rn(qnv[mt][i2], knv[nt][j2]), 1e-8f);
                float cosv = __fdiv_rn(d[mt][nt][r], denom);
                float dx = __fsub_rn(qxv[mt][i2], kxv[nt][j2]);
                float dy = __fsub_rn(qyv[mt][i2], kyv[nt][j2]);
                float d2v = __fadd_rn(__fmul_rn(dx, dx), __fmul_rn(dy, dy));
                float dist = __fdiv_rn(__fsqrt_rn(d2v), maxdiag);
                if (dist < 16.0f) {   // pos_ratio * H = 0.5 * 32
                    lsum += cosv;
                    lcnt += 1.0f;
                }
            }
        }
    }

    redS[tid] = lsum;
    redC[tid] = lcnt;
    __syncthreads();
#pragma unroll
    for (int s = 128; s > 0; s >>= 1) {
        if (tid < s) { redS[tid] += redS[tid + s]; redC[tid] += redC[tid + s]; }
        __syncthreads();
    }
    if (tid == 0) {
        atomicAdd(&g_sum[z], (double)redS[0]);
        atomicAdd(&g_cnt[z], (double)redC[0]);
    }
}

__global__ void final_kernel(float* __restrict__ out) {
    double l1 = 0.0, l2 = 0.0;
    for (int n = 0; n < 32; ++n) {
        l1 += g_sum[n]      / (g_cnt[n]      + 1e-6);
        l2 += g_sum[32 + n] / (g_cnt[32 + n] + 1e-6);
    }
    out[0] = (float)(-((l1 / 32.0) + (l2 / 32.0)) * 0.5);
}

// ---------------- launch ----------------
extern "C" void kernel_launch(void* const* d_in, const int* in_sizes, int n_in,
                              void* d_out, int out_size) {
    const float* p1 = (const float*)d_in[0];
    const float* p2 = (const float*)d_in[1];
    const float* z1 = (const float*)d_in[2];
    const float* z2 = (const float*)d_in[3];
    const float* c1 = (const float*)d_in[4];
    const float* c2 = (const float*)d_in[5];
    float* out = (float*)d_out;

    zero_kernel<<<1, 64>>>();
    centers_kernel<<<NB, 1024>>>(c1, c2);
    prep_kernel<<<dim3(32, NB, 4), 256>>>(p1, p2, z1, z2);
    gemm_loss_kernel<<<dim3(8, 16, 64), 256>>>();
    final_kernel<<<1, 1>>>(out);
}

// round 11
// speedup vs baseline: 1.2949x; 1.2439x over previous
#include <cuda_runtime.h>
#include <math.h>
#include <stdint.h>

// Problem constants (fixed by reference: N=32, C=256, H=W=32)
#define NB 32
#define CDIM 256
#define HW 1024
#define WD 32

// ---------------- device scratch (no allocations allowed) ----------------
__device__ double g_sum[64];                 // masked cos sum per (loss, n)
__device__ double g_cnt[64];                 // mask count per (loss, n)
__device__ float  g_ninv[4][NB * HW];        // 1/||.|| for p1,p2,z1,z2
__device__ float  g_cx[2][NB * HW];          // centers x for coord_1, coord_2
__device__ float  g_cy[2][NB * HW];          // centers y
__device__ float  g_maxdiag[NB];             // max(diag1, diag2) per n
// TF32-quantized, transposed copies: [t][n][p][k], row = 256 floats (1KB).
__device__ float  g_tf32[4ull * NB * HW * CDIM];   // 134 MB

// Round fp32 -> TF32 (10-bit mantissa), same conversion cuBLAS/CUTLASS use.
__device__ __forceinline__ float tf32r(float x) {
    uint32_t u;
    asm("cvt.rna.tf32.f32 %0, %1;" : "=r"(u) : "f"(x));
    return __uint_as_float(u);
}

// m16n8k8 TF32 MMA, fp32 accumulate
__device__ __forceinline__ void mma_tf32(float* d,
                                         float a0, float a1, float a2, float a3,
                                         float b0, float b1) {
    asm volatile(
        "mma.sync.aligned.m16n8k8.row.col.f32.tf32.tf32.f32 "
        "{%0,%1,%2,%3}, {%4,%5,%6,%7}, {%8,%9}, {%0,%1,%2,%3};\n"
        : "+f"(d[0]), "+f"(d[1]), "+f"(d[2]), "+f"(d[3])
        : "r"(__float_as_uint(a0)), "r"(__float_as_uint(a1)),
          "r"(__float_as_uint(a2)), "r"(__float_as_uint(a3)),
          "r"(__float_as_uint(b0)), "r"(__float_as_uint(b1)));
}

#define CP_ASYNC16(dst32, srcp) \
    asm volatile("cp.async.cg.shared.global [%0], [%1], 16;\n" :: "r"(dst32), "l"(srcp))
#define CP_COMMIT() asm volatile("cp.async.commit_group;\n")
#define CP_WAIT(n)  asm volatile("cp.async.wait_group %0;\n" :: "n"(n))

// ---------------- kernels ----------------
__global__ void zero_kernel() {
    int i = threadIdx.x;
    if (i < 64) { g_sum[i] = 0.0; g_cnt[i] = 0.0; }
}

// grid (NB), block 1024: centers + max_diag, exact reference arithmetic.
__global__ void centers_kernel(const float* __restrict__ c1, const float* __restrict__ c2) {
    int n = blockIdx.x;
    int p = threadIdx.x;
    float a0 = c1[n * 4 + 0], a1 = c1[n * 4 + 1], a2 = c1[n * 4 + 2], a3 = c1[n * 4 + 3];
    float b0 = c2[n * 4 + 0], b1 = c2[n * 4 + 1], b2 = c2[n * 4 + 2], b3 = c2[n * 4 + 3];
    float bw1 = __fdiv_rn(__fsub_rn(a2, a0), 32.0f), bh1 = __fdiv_rn(__fsub_rn(a3, a1), 32.0f);
    float bw2 = __fdiv_rn(__fsub_rn(b2, b0), 32.0f), bh2 = __fdiv_rn(__fsub_rn(b3, b1), 32.0f);
    float x = (float)(p % WD);
    float y = (float)(p / WD);
    g_cx[0][n * HW + p] = __fadd_rn(__fmul_rn(__fadd_rn(x, 0.5f), bw1), a0);
    g_cy[0][n * HW + p] = __fadd_rn(__fmul_rn(__fadd_rn(y, 0.5f), bh1), a1);
    g_cx[1][n * HW + p] = __fadd_rn(__fmul_rn(__fadd_rn(x, 0.5f), bw2), b0);
    g_cy[1][n * HW + p] = __fadd_rn(__fmul_rn(__fadd_rn(y, 0.5f), bh2), b1);
    if (p == 0) {
        float d1 = __fsqrt_rn(__fadd_rn(__fmul_rn(bw1, bw1), __fmul_rn(bh1, bh1)));
        float d2 = __fsqrt_rn(__fadd_rn(__fmul_rn(bw2, bw2), __fmul_rn(bh2, bh2)));
        g_maxdiag[n] = fmaxf(d1, d2);
    }
}

// Fused prep: transpose [c][p] -> [p][c], TF32-quantize into g_tf32, AND
// accumulate exact-fp32 column norms (stored as inverses) in the same pass.
// grid (32 ptiles, NB, 4), block 256. 32x32 smem tile.
__global__ __launch_bounds__(256) void prep_kernel(
    const float* __restrict__ p1, const float* __restrict__ p2,
    const float* __restrict__ z1, const float* __restrict__ z2) {
    int t = blockIdx.z;
    int n = blockIdx.y;
    int p0 = blockIdx.x * 32;
    const float* src = (t == 0) ? p1 : (t == 1) ? p2 : (t == 2) ? z1 : z2;
    src += (size_t)n * CDIM * HW;
    float* dst = g_tf32 + ((size_t)(t * NB + n) * HW) * CDIM;

    __shared__ float s[32][33];
    __shared__ float part[8][32];
    int tid = threadIdx.x;
    int rc = tid >> 5;        // 0..7
    int rp = tid & 31;        // 0..31
    float acc = 0.f;

#pragma unroll 1
    for (int ct = 0; ct < 8; ++ct) {
        int c0 = ct * 32;
#pragma unroll
        for (int j = 0; j < 4; ++j) {
            int c = rc + j * 8;
            s[c][rp] = src[(size_t)(c0 + c) * HW + p0 + rp];
        }
        __syncthreads();
        // norms: group rc handles c in {4rc..4rc+3}, column rp
#pragma unroll
        for (int i = 0; i < 4; ++i) {
            float v = s[rc * 4 + i][rp];
            acc += v * v;
        }
        // transposed quantized write: lane = c within tile
#pragma unroll
        for (int j = 0; j < 4; ++j) {
            int p = rc + j * 8;
            dst[(size_t)(p0 + p) * CDIM + c0 + rp] = tf32r(s[rp][p]);
        }
        __syncthreads();
    }
    part[rc][rp] = acc;
    __syncthreads();
    if (tid < 32) {
        float n2 = 0.f;
#pragma unroll
        for (int g = 0; g < 8; ++g) n2 += part[g][tid];
        g_ninv[t][n * HW + p0 + tid] = 1.0f / sqrtf(n2);
    }
}

// Fused TF32 tensor-core GEMM + cosine + mask + masked-mean reduction.
// 128(p) x 64(q) tile, BK=16, 3-stage cp.async ring, one barrier per stage.
// k-loop FULLY UNROLLED. Mask arithmetic is BIT-EXACT with the reference
// (sqrt.rn then div.rn then compare) -- threshold semantics must not drift.
#define BM 128
#define BNQ 64
#define BK 16
#define NSTG 3
#define NT (CDIM / BK)    // 16 k-tiles

__global__ __launch_bounds__(256, 3) void gemm_loss_kernel() {
    int z = blockIdx.z;          // 0..63 : (loss, n)
    int n = z & 31;
    int which = z >> 5;          // 0 -> (p1, z2), 1 -> (p2, z1)

    const float *Q, *K, *qiv, *kiv, *qcx, *qcy, *kcx, *kcy;
    if (which == 0) {
        Q = g_tf32 + ((size_t)(0 * NB + n) * HW) * CDIM;
        K = g_tf32 + ((size_t)(3 * NB + n) * HW) * CDIM;
        qiv = &g_ninv[0][n * HW]; kiv = &g_ninv[3][n * HW];
        qcx = &g_cx[0][n * HW]; qcy = &g_cy[0][n * HW];
        kcx = &g_cx[1][n * HW]; kcy = &g_cy[1][n * HW];
    } else {
        Q = g_tf32 + ((size_t)(1 * NB + n) * HW) * CDIM;
        K = g_tf32 + ((size_t)(2 * NB + n) * HW) * CDIM;
        qiv = &g_ninv[1][n * HW]; kiv = &g_ninv[2][n * HW];
        qcx = &g_cx[1][n * HW]; qcy = &g_cy[1][n * HW];
        kcx = &g_cx[0][n * HW]; kcy = &g_cy[0][n * HW];
    }
    float maxdiag = g_maxdiag[n];

    __shared__ float As3[NSTG][BM][BK];     // 24 KB
    __shared__ float Bs3[NSTG][BNQ][BK];    // 12 KB
    __shared__ float redS[256];
    __shared__ float redC[256];

    int tid  = threadIdx.x;
    int lane = tid & 31;
    int warp = tid >> 5;          // 0..7
    int gid  = lane >> 2;         // 0..7
    int tig  = lane & 3;          // 0..3
    int warpM = warp >> 1;        // 0..3 -> 32-row band
    int warpN = warp & 1;         // 0..1 -> 32-col band
    int pBase = blockIdx.x * BM;
    int qBase = blockIdx.y * BNQ;

    // cp.async mapping: cr = row (0..63), co = float offset of 16B chunk
    int cr = tid >> 2;            // 0..63
    int co = (tid & 3) * 4;       // 0,4,8,12

    uint32_t sA = (uint32_t)__cvta_generic_to_shared(&As3[0][0][0]);
    uint32_t sB = (uint32_t)__cvta_generic_to_shared(&Bs3[0][0][0]);
    const uint32_t aBuf = BM * BK * 4;    // 8 KB
    const uint32_t bBuf = BNQ * BK * 4;   // 4 KB
    uint32_t thOff = (uint32_t)((cr * BK + co) * 4);
    const float* qRow0 = Q + (size_t)(pBase + cr) * CDIM + co;
    const float* qRow1 = Q + (size_t)(pBase + cr + 64) * CDIM + co;
    const float* kRow  = K + (size_t)(qBase + cr) * CDIM + co;

    float d[2][4][4];
#pragma unroll
    for (int mt = 0; mt < 2; ++mt)
#pragma unroll
        for (int nt = 0; nt < 4; ++nt)
#pragma unroll
            for (int r = 0; r < 4; ++r) d[mt][nt][r] = 0.f;

    // prologue: issue stages 0 and 1 as separate groups
#pragma unroll
    for (int st = 0; st < 2; ++st) {
        CP_ASYNC16(sA + st * aBuf + thOff, qRow0 + st * BK);
        CP_ASYNC16(sA + st * aBuf + thOff + 64u * BK * 4u, qRow1 + st * BK);
        CP_ASYNC16(sB + st * bBuf + thOff, kRow + st * BK);
        CP_COMMIT();
    }

#pragma unroll
    for (int kt = 0; kt < NT; ++kt) {
        const int cur  = kt % NSTG;
        const int nxt2 = (kt + 2) % NSTG;
        if (kt < NT - 1) { CP_WAIT(1); } else { CP_WAIT(0); }
        __syncthreads();   // stage kt visible; fences reuse of buffer nxt2
        if (kt + 2 < NT) {
            CP_ASYNC16(sA + nxt2 * aBuf + thOff, qRow0 + (kt + 2) * BK);
            CP_ASYNC16(sA + nxt2 * aBuf + thOff + 64u * BK * 4u, qRow1 + (kt + 2) * BK);
            CP_ASYNC16(sB + nxt2 * bBuf + thOff, kRow + (kt + 2) * BK);
            CP_COMMIT();
        }
        // B fragments: one float4 per nt covers both k8 steps
        float4 wb[4];
#pragma unroll
        for (int nt = 0; nt < 4; ++nt)
            wb[nt] = *(const float4*)&Bs3[cur][warpN * 32 + nt * 8 + gid][tig * 4];
#pragma unroll
        for (int mt = 0; mt < 2; ++mt) {
            int pm = warpM * 32 + mt * 16 + gid;
            float4 va = *(const float4*)&As3[cur][pm][tig * 4];
            float4 vb = *(const float4*)&As3[cur][pm + 8][tig * 4];
#pragma unroll
            for (int nt = 0; nt < 4; ++nt)
                mma_tf32(d[mt][nt], va.x, vb.x, va.y, vb.y, wb[nt].x, wb[nt].y);
#pragma unroll
            for (int nt = 0; nt < 4; ++nt)
                mma_tf32(d[mt][nt], va.z, vb.z, va.w, vb.w, wb[nt].z, wb[nt].w);
        }
    }

    // Epilogue: cos = sim * qinv * kinv (smooth path, safe);
    // mask = BIT-EXACT reference chain: sqrt.rn -> div.rn -> compare.
    float qnv[2][2], qxv[2][2], qyv[2][2];
#pragma unroll
    for (int mt = 0; mt < 2; ++mt)
#pragma unroll
        for (int i2 = 0; i2 < 2; ++i2) {
            int p = pBase + warpM * 32 + mt * 16 + gid + i2 * 8;
            qnv[mt][i2] = qiv[p]; qxv[mt][i2] = qcx[p]; qyv[mt][i2] = qcy[p];
        }
    float knv[4][2], kxv[4][2], kyv[4][2];
#pragma unroll
    for (int nt = 0; nt < 4; ++nt)
#pragma unroll
        for (int j2 = 0; j2 < 2; ++j2) {
            int q = qBase + warpN * 32 + nt * 8 + 2 * tig + j2;
            knv[nt][j2] = kiv[q]; kxv[nt][j2] = kcx[q]; kyv[nt][j2] = kcy[q];
        }

    float lsum = 0.f, lcnt = 0.f;
#pragma unroll
    for (int mt = 0; mt < 2; ++mt) {
#pragma unroll
        for (int nt = 0; nt < 4; ++nt) {
#pragma unroll
            for (int r = 0; r < 4; ++r) {
                int i2 = r >> 1, j2 = r & 1;
                float cosv = d[mt][nt][r] * qnv[mt][i2] * knv[nt][j2];
                float dx = __fsub_rn(qxv[mt][i2], kxv[nt][j2]);
                float dy = __fsub_rn(qyv[mt][i2], kyv[nt][j2]);
                float d2v = __fadd_rn(__fmul_rn(dx, dx), __fmul_rn(dy, dy));
                float dist = __fdiv_rn(__fsqrt_rn(d2v), maxdiag);
                if (dist < 16.0f) {   // pos_ratio * H = 0.5 * 32
                    lsum += cosv;
                    lcnt += 1.0f;
                }
            }
        }
    }

    redS[tid] = lsum;
    redC[tid] = lcnt;
    __syncthreads();
#pragma unroll
    for (int s = 128; s > 0; s >>= 1) {
        if (tid < s) { redS[tid] += redS[tid + s]; redC[tid] += redC[tid + s]; }
        __syncthreads();
    }
    if (tid == 0) {
        atomicAdd(&g_sum[z], (double)redS[0]);
        atomicAdd(&g_cnt[z], (double)redC[0]);
    }
}

__global__ void final_kernel(float* __restrict__ out) {
    double l1 = 0.0, l2 = 0.0;
    for (int n = 0; n < 32; ++n) {
        l1 += g_sum[n]      / (g_cnt[n]      + 1e-6);
        l2 += g_sum[32 + n] / (g_cnt[32 + n] + 1e-6);
    }
    out[0] = (float)(-((l1 / 32.0) + (l2 / 32.0)) * 0.5);
}

// ---------------- launch ----------------
extern "C" void kernel_launch(void* const* d_in, const int* in_sizes, int n_in,
                              void* d_out, int out_size) {
    const float* p1 = (const float*)d_in[0];
    const float* p2 = (const float*)d_in[1];
    const float* z1 = (const float*)d_in[2];
    const float* z2 = (const float*)d_in[3];
    const float* c1 = (const float*)d_in[4];
    const float* c2 = (const float*)d_in[5];
    float* out = (float*)d_out;

    zero_kernel<<<1, 64>>>();
    centers_kernel<<<NB, 1024>>>(c1, c2);
    prep_kernel<<<dim3(32, NB, 4), 256>>>(p1, p2, z1, z2);
    gemm_loss_kernel<<<dim3(8, 16, 64), 256>>>();
    final_kernel<<<1, 1>>>(out);
}

// round 13
// speedup vs baseline: 1.5076x; 1.1643x over previous
#include <cuda_runtime.h>
#include <math.h>
#include <stdint.h>

// Problem constants (fixed by reference: N=32, C=256, H=W=32)
#define NB 32
#define CDIM 256
#define HW 1024
#define WD 32

// ---------------- device scratch (no allocations allowed) ----------------
__device__ double g_sum[64];                 // masked cos sum per (loss, n)
__device__ double g_cnt[64];                 // mask count per (loss, n)
__device__ float  g_ninv[4][NB * HW];        // 1/||.|| for p1,p2,z1,z2
__device__ float  g_cx[2][NB * HW];          // centers x for coord_1, coord_2
__device__ float  g_cy[2][NB * HW];          // centers y
__device__ float  g_dthr2[NB];               // EXACT d2 threshold (see below)
// TF32-quantized, transposed copies: [t][n][p][k], row = 256 floats (1KB).
__device__ float  g_tf32[4ull * NB * HW * CDIM];   // 134 MB

// Round fp32 -> TF32 (10-bit mantissa), same conversion cuBLAS/CUTLASS use.
__device__ __forceinline__ float tf32r(float x) {
    uint32_t u;
    asm("cvt.rna.tf32.f32 %0, %1;" : "=r"(u) : "f"(x));
    return __uint_as_float(u);
}

// m16n8k8 TF32 MMA, fp32 accumulate
__device__ __forceinline__ void mma_tf32(float* d,
                                         float a0, float a1, float a2, float a3,
                                         float b0, float b1) {
    asm volatile(
        "mma.sync.aligned.m16n8k8.row.col.f32.tf32.tf32.f32 "
        "{%0,%1,%2,%3}, {%4,%5,%6,%7}, {%8,%9}, {%0,%1,%2,%3};\n"
        : "+f"(d[0]), "+f"(d[1]), "+f"(d[2]), "+f"(d[3])
        : "r"(__float_as_uint(a0)), "r"(__float_as_uint(a1)),
          "r"(__float_as_uint(a2)), "r"(__float_as_uint(a3)),
          "r"(__float_as_uint(b0)), "r"(__float_as_uint(b1)));
}

#define CP_ASYNC16(dst32, srcp) \
    asm volatile("cp.async.cg.shared.global [%0], [%1], 16;\n" :: "r"(dst32), "l"(srcp))
#define CP_COMMIT() asm volatile("cp.async.commit_group;\n")
#define CP_WAIT(n)  asm volatile("cp.async.wait_group %0;\n" :: "n"(n))

// ---------------- kernels ----------------
__global__ void zero_kernel() {
    int i = threadIdx.x;
    if (i < 64) { g_sum[i] = 0.0; g_cnt[i] = 0.0; }
}

// grid (NB), block 1024: centers + EXACT d2 mask threshold.
// The reference mask is  __fdiv_rn(__fsqrt_rn(d2), md) < 16.0f,  which is a
// monotone nondecreasing function of d2 (composition of rounded monotone
// functions). Hence there is a float T with  mask <=> d2 < T.  We find T by
// a binary search over the nonneg-float bit order. Bit-exact.
__global__ void centers_kernel(const float* __restrict__ c1, const float* __restrict__ c2) {
    int n = blockIdx.x;
    int p = threadIdx.x;
    float a0 = c1[n * 4 + 0], a1 = c1[n * 4 + 1], a2 = c1[n * 4 + 2], a3 = c1[n * 4 + 3];
    float b0 = c2[n * 4 + 0], b1 = c2[n * 4 + 1], b2 = c2[n * 4 + 2], b3 = c2[n * 4 + 3];
    float bw1 = __fdiv_rn(__fsub_rn(a2, a0), 32.0f), bh1 = __fdiv_rn(__fsub_rn(a3, a1), 32.0f);
    float bw2 = __fdiv_rn(__fsub_rn(b2, b0), 32.0f), bh2 = __fdiv_rn(__fsub_rn(b3, b1), 32.0f);
    float x = (float)(p % WD);
    float y = (float)(p / WD);
    g_cx[0][n * HW + p] = __fadd_rn(__fmul_rn(__fadd_rn(x, 0.5f), bw1), a0);
    g_cy[0][n * HW + p] = __fadd_rn(__fmul_rn(__fadd_rn(y, 0.5f), bh1), a1);
    g_cx[1][n * HW + p] = __fadd_rn(__fmul_rn(__fadd_rn(x, 0.5f), bw2), b0);
    g_cy[1][n * HW + p] = __fadd_rn(__fmul_rn(__fadd_rn(y, 0.5f), bh2), b1);
    if (p == 0) {
        float d1 = __fsqrt_rn(__fadd_rn(__fmul_rn(bw1, bw1), __fmul_rn(bh1, bh1)));
        float d2 = __fsqrt_rn(__fadd_rn(__fmul_rn(bw2, bw2), __fmul_rn(bh2, bh2)));
        float md = fmaxf(d1, d2);
        // binary search: smallest nonneg float v with div(sqrt(v), md) >= 16
        uint32_t lo = 0u, hi = 0x7F7FFFFFu;   // [0, FLT_MAX]
        while (lo < hi) {
            uint32_t mid = lo + ((hi - lo) >> 1);
            float v = __uint_as_float(mid);
            if (__fdiv_rn(__fsqrt_rn(v), md) >= 16.0f) hi = mid;
            else lo = mid + 1;
        }
        g_dthr2[n] = __uint_as_float(lo);     // mask <=> d2 < g_dthr2[n]
    }
}

// Fused prep: transpose [c][p] -> [p][c], TF32-quantize into g_tf32, AND
// accumulate exact-fp32 column norms (stored as inverses) in the same pass.
// grid (32 ptiles, NB, 4), block 256. 32x32 smem tile.
__global__ __launch_bounds__(256) void prep_kernel(
    const float* __restrict__ p1, const float* __restrict__ p2,
    const float* __restrict__ z1, const float* __restrict__ z2) {
    int t = blockIdx.z;
    int n = blockIdx.y;
    int p0 = blockIdx.x * 32;
    const float* src = (t == 0) ? p1 : (t == 1) ? p2 : (t == 2) ? z1 : z2;
    src += (size_t)n * CDIM * HW;
    float* dst = g_tf32 + ((size_t)(t * NB + n) * HW) * CDIM;

    __shared__ float s[32][33];
    __shared__ float part[8][32];
    int tid = threadIdx.x;
    int rc = tid >> 5;        // 0..7
    int rp = tid & 31;        // 0..31
    float acc = 0.f;

#pragma unroll 1
    for (int ct = 0; ct < 8; ++ct) {
        int c0 = ct * 32;
#pragma unroll
        for (int j = 0; j < 4; ++j) {
            int c = rc + j * 8;
            s[c][rp] = src[(size_t)(c0 + c) * HW + p0 + rp];
        }
        __syncthreads();
#pragma unroll
        for (int i = 0; i < 4; ++i) {
            float v = s[rc * 4 + i][rp];
            acc += v * v;
        }
#pragma unroll
        for (int j = 0; j < 4; ++j) {
            int p = rc + j * 8;
            dst[(size_t)(p0 + p) * CDIM + c0 + rp] = tf32r(s[rp][p]);
        }
        __syncthreads();
    }
    part[rc][rp] = acc;
    __syncthreads();
    if (tid < 32) {
        float n2 = 0.f;
#pragma unroll
        for (int g = 0; g < 8; ++g) n2 += part[g][tid];
        g_ninv[t][n * HW + p0 + tid] = 1.0f / sqrtf(n2);
    }
}

// Fused TF32 tensor-core GEMM + cosine + mask + masked-mean reduction.
// 128(p) x 64(q) tile, BK=16, 3-stage cp.async ring, one barrier per stage.
// k-loop FULLY UNROLLED. Mask = (d2 < T) with T the EXACT monotone-equivalent
// threshold of the reference's sqrt/div/compare chain.
#define BM 128
#define BNQ 64
#define BK 16
#define NSTG 3
#define NT (CDIM / BK)    // 16 k-tiles

__global__ __launch_bounds__(256, 3) void gemm_loss_kernel() {
    int z = blockIdx.z;          // 0..63 : (loss, n)
    int n = z & 31;
    int which = z >> 5;          // 0 -> (p1, z2), 1 -> (p2, z1)

    const float *Q, *K, *qiv, *kiv, *qcx, *qcy, *kcx, *kcy;
    if (which == 0) {
        Q = g_tf32 + ((size_t)(0 * NB + n) * HW) * CDIM;
        K = g_tf32 + ((size_t)(3 * NB + n) * HW) * CDIM;
        qiv = &g_ninv[0][n * HW]; kiv = &g_ninv[3][n * HW];
        qcx = &g_cx[0][n * HW]; qcy = &g_cy[0][n * HW];
        kcx = &g_cx[1][n * HW]; kcy = &g_cy[1][n * HW];
    } else {
        Q = g_tf32 + ((size_t)(1 * NB + n) * HW) * CDIM;
        K = g_tf32 + ((size_t)(2 * NB + n) * HW) * CDIM;
        qiv = &g_ninv[1][n * HW]; kiv = &g_ninv[2][n * HW];
        qcx = &g_cx[1][n * HW]; qcy = &g_cy[1][n * HW];
        kcx = &g_cx[0][n * HW]; kcy = &g_cy[0][n * HW];
    }
    float dthr2 = g_dthr2[n];

    __shared__ float As3[NSTG][BM][BK];     // 24 KB
    __shared__ float Bs3[NSTG][BNQ][BK];    // 12 KB
    __shared__ float warpS[8];
    __shared__ float warpC[8];

    int tid  = threadIdx.x;
    int lane = tid & 31;
    int warp = tid >> 5;          // 0..7
    int gid  = lane >> 2;         // 0..7
    int tig  = lane & 3;          // 0..3
    int warpM = warp >> 1;        // 0..3 -> 32-row band
    int warpN = warp & 1;         // 0..1 -> 32-col band
    int pBase = blockIdx.x * BM;
    int qBase = blockIdx.y * BNQ;

    // cp.async mapping: cr = row (0..63), co = float offset of 16B chunk
    int cr = tid >> 2;            // 0..63
    int co = (tid & 3) * 4;       // 0,4,8,12

    uint32_t sA = (uint32_t)__cvta_generic_to_shared(&As3[0][0][0]);
    uint32_t sB = (uint32_t)__cvta_generic_to_shared(&Bs3[0][0][0]);
    const uint32_t aBuf = BM * BK * 4;    // 8 KB
    const uint32_t bBuf = BNQ * BK * 4;   // 4 KB
    uint32_t thOff = (uint32_t)((cr * BK + co) * 4);
    const float* qRow0 = Q + (size_t)(pBase + cr) * CDIM + co;
    const float* qRow1 = Q + (size_t)(pBase + cr + 64) * CDIM + co;
    const float* kRow  = K + (size_t)(qBase + cr) * CDIM + co;

    float d[2][4][4];
#pragma unroll
    for (int mt = 0; mt < 2; ++mt)
#pragma unroll
        for (int nt = 0; nt < 4; ++nt)
#pragma unroll
            for (int r = 0; r < 4; ++r) d[mt][nt][r] = 0.f;

    // prologue: issue stages 0 and 1 as separate groups
#pragma unroll
    for (int st = 0; st < 2; ++st) {
        CP_ASYNC16(sA + st * aBuf + thOff, qRow0 + st * BK);
        CP_ASYNC16(sA + st * aBuf + thOff + 64u * BK * 4u, qRow1 + st * BK);
        CP_ASYNC16(sB + st * bBuf + thOff, kRow + st * BK);
        CP_COMMIT();
    }

#pragma unroll
    for (int kt = 0; kt < NT; ++kt) {
        const int cur  = kt % NSTG;
        const int nxt2 = (kt + 2) % NSTG;
        if (kt < NT - 1) { CP_WAIT(1); } else { CP_WAIT(0); }
        __syncthreads();   // stage kt visible; fences reuse of buffer nxt2
        if (kt + 2 < NT) {
            CP_ASYNC16(sA + nxt2 * aBuf + thOff, qRow0 + (kt + 2) * BK);
            CP_ASYNC16(sA + nxt2 * aBuf + thOff + 64u * BK * 4u, qRow1 + (kt + 2) * BK);
            CP_ASYNC16(sB + nxt2 * bBuf + thOff, kRow + (kt + 2) * BK);
            CP_COMMIT();
        }
        // B fragments: one float4 per nt covers both k8 steps
        float4 wb[4];
#pragma unroll
        for (int nt = 0; nt < 4; ++nt)
            wb[nt] = *(const float4*)&Bs3[cur][warpN * 32 + nt * 8 + gid][tig * 4];
#pragma unroll
        for (int mt = 0; mt < 2; ++mt) {
            int pm = warpM * 32 + mt * 16 + gid;
            float4 va = *(const float4*)&As3[cur][pm][tig * 4];
            float4 vb = *(const float4*)&As3[cur][pm + 8][tig * 4];
#pragma unroll
            for (int nt = 0; nt < 4; ++nt)
                mma_tf32(d[mt][nt], va.x, vb.x, va.y, vb.y, wb[nt].x, wb[nt].y);
#pragma unroll
            for (int nt = 0; nt < 4; ++nt)
                mma_tf32(d[mt][nt], va.z, vb.z, va.w, vb.w, wb[nt].z, wb[nt].w);
        }
    }

    // Epilogue: cos = sim * qinv * kinv; mask = (d2 < dthr2), bit-exact
    // equivalent of the reference sqrt/div/compare (monotone reduction).
    float qnv[2][2], qxv[2][2], qyv[2][2];
#pragma unroll
    for (int mt = 0; mt < 2; ++mt)
#pragma unroll
        for (int i2 = 0; i2 < 2; ++i2) {
            int p = pBase + warpM * 32 + mt * 16 + gid + i2 * 8;
            qnv[mt][i2] = qiv[p]; qxv[mt][i2] = qcx[p]; qyv[mt][i2] = qcy[p];
        }
    float knv[4][2], kxv[4][2], kyv[4][2];
#pragma unroll
    for (int nt = 0; nt < 4; ++nt)
#pragma unroll
        for (int j2 = 0; j2 < 2; ++j2) {
            int q = qBase + warpN * 32 + nt * 8 + 2 * tig + j2;
            knv[nt][j2] = kiv[q]; kxv[nt][j2] = kcx[q]; kyv[nt][j2] = kcy[q];
        }

    float lsum = 0.f, lcnt = 0.f;
#pragma unroll
    for (int mt = 0; mt < 2; ++mt) {
#pragma unroll
        for (int nt = 0; nt < 4; ++nt) {
#pragma unroll
            for (int r = 0; r < 4; ++r) {
                int i2 = r >> 1, j2 = r & 1;
                float cosv = d[mt][nt][r] * qnv[mt][i2] * knv[nt][j2];
                float dx = __fsub_rn(qxv[mt][i2], kxv[nt][j2]);
                float dy = __fsub_rn(qyv[mt][i2], kyv[nt][j2]);
                float d2v = __fadd_rn(__fmul_rn(dx, dx), __fmul_rn(dy, dy));
                if (d2v < dthr2) {
                    lsum += cosv;
                    lcnt += 1.0f;
                }
            }
        }
    }

    // warp-shuffle reduction, then one cross-warp pass, then fp64 atomics
#pragma unroll
    for (int sh = 16; sh > 0; sh >>= 1) {
        lsum += __shfl_xor_sync(0xFFFFFFFFu, lsum, sh);
        lcnt += __shfl_xor_sync(0xFFFFFFFFu, lcnt, sh);
    }
    if (lane == 0) { warpS[warp] = lsum; warpC[warp] = lcnt; }
    __syncthreads();
    if (warp == 0 && lane == 0) {
        float ts = 0.f, tc = 0.f;
#pragma unroll
        for (int w = 0; w < 8; ++w) { ts += warpS[w]; tc += warpC[w]; }
        atomicAdd(&g_sum[z], (double)ts);
        atomicAdd(&g_cnt[z], (double)tc);
    }
}

__global__ void final_kernel(float* __restrict__ out) {
    double l1 = 0.0, l2 = 0.0;
    for (int n = 0; n < 32; ++n) {
        l1 += g_sum[n]      / (g_cnt[n]      + 1e-6);
        l2 += g_sum[32 + n] / (g_cnt[32 + n] + 1e-6);
    }
    out[0] = (float)(-((l1 / 32.0) + (l2 / 32.0)) * 0.5);
}

// ---------------- launch ----------------
extern "C" void kernel_launch(void* const* d_in, const int* in_sizes, int n_in,
                              void* d_out, int out_size) {
    const float* p1 = (const float*)d_in[0];
    const float* p2 = (const float*)d_in[1];
    const float* z1 = (const float*)d_in[2];
    const float* z2 = (const float*)d_in[3];
    const float* c1 = (const float*)d_in[4];
    const float* c2 = (const float*)d_in[5];
    float* out = (float*)d_out;

    zero_kernel<<<1, 64>>>();
    centers_kernel<<<NB, 1024>>>(c1, c2);
    prep_kernel<<<dim3(32, NB, 4), 256>>>(p1, p2, z1, z2);
    gemm_loss_kernel<<<dim3(8, 16, 64), 256>>>();
    final_kernel<<<1, 1>>>(out);
}

// round 14
// speedup vs baseline: 1.5153x; 1.0051x over previous
#include <cuda_runtime.h>
#include <math.h>
#include <stdint.h>

// Problem constants (fixed by reference: N=32, C=256, H=W=32)
#define NB 32
#define CDIM 256
#define HW 1024
#define WD 32

// ---------------- device scratch (no allocations allowed) ----------------
__device__ double g_sum[64];                 // masked cos sum per (loss, n)
__device__ double g_cnt[64];                 // mask count per (loss, n)
__device__ float  g_ninv[4][NB * HW];        // 1/||.|| for p1,p2,z1,z2
__device__ float  g_cx[2][NB * HW];          // centers x for coord_1, coord_2
__device__ float  g_cy[2][NB * HW];          // centers y
__device__ float  g_dthr2[NB];               // EXACT d2 threshold (see below)
// TF32-quantized, transposed copies: [t][n][p][k], row = 256 floats (1KB).
__device__ float  g_tf32[4ull * NB * HW * CDIM];   // 134 MB

// Round fp32 -> TF32 (10-bit mantissa), same conversion cuBLAS/CUTLASS use.
__device__ __forceinline__ float tf32r(float x) {
    uint32_t u;
    asm("cvt.rna.tf32.f32 %0, %1;" : "=r"(u) : "f"(x));
    return __uint_as_float(u);
}

// m16n8k8 TF32 MMA, fp32 accumulate
__device__ __forceinline__ void mma_tf32(float* d,
                                         float a0, float a1, float a2, float a3,
                                         float b0, float b1) {
    asm volatile(
        "mma.sync.aligned.m16n8k8.row.col.f32.tf32.tf32.f32 "
        "{%0,%1,%2,%3}, {%4,%5,%6,%7}, {%8,%9}, {%0,%1,%2,%3};\n"
        : "+f"(d[0]), "+f"(d[1]), "+f"(d[2]), "+f"(d[3])
        : "r"(__float_as_uint(a0)), "r"(__float_as_uint(a1)),
          "r"(__float_as_uint(a2)), "r"(__float_as_uint(a3)),
          "r"(__float_as_uint(b0)), "r"(__float_as_uint(b1)));
}

#define CP_ASYNC16(dst32, srcp) \
    asm volatile("cp.async.cg.shared.global [%0], [%1], 16;\n" :: "r"(dst32), "l"(srcp))
#define CP_COMMIT() asm volatile("cp.async.commit_group;\n")
#define CP_WAIT(n)  asm volatile("cp.async.wait_group %0;\n" :: "n"(n))

// ---------------- kernels ----------------
__global__ void zero_kernel() {
    int i = threadIdx.x;
    if (i < 64) { g_sum[i] = 0.0; g_cnt[i] = 0.0; }
}

// grid (NB), block 1024: centers + EXACT d2 mask threshold.
// Reference mask  __fdiv_rn(__fsqrt_rn(d2), md) < 16  is monotone in d2, so
// a bit-level binary search yields T with mask <=> d2 < T, bit-exactly.
__global__ void centers_kernel(const float* __restrict__ c1, const float* __restrict__ c2) {
    int n = blockIdx.x;
    int p = threadIdx.x;
    float a0 = c1[n * 4 + 0], a1 = c1[n * 4 + 1], a2 = c1[n * 4 + 2], a3 = c1[n * 4 + 3];
    float b0 = c2[n * 4 + 0], b1 = c2[n * 4 + 1], b2 = c2[n * 4 + 2], b3 = c2[n * 4 + 3];
    float bw1 = __fdiv_rn(__fsub_rn(a2, a0), 32.0f), bh1 = __fdiv_rn(__fsub_rn(a3, a1), 32.0f);
    float bw2 = __fdiv_rn(__fsub_rn(b2, b0), 32.0f), bh2 = __fdiv_rn(__fsub_rn(b3, b1), 32.0f);
    float x = (float)(p % WD);
    float y = (float)(p / WD);
    g_cx[0][n * HW + p] = __fadd_rn(__fmul_rn(__fadd_rn(x, 0.5f), bw1), a0);
    g_cy[0][n * HW + p] = __fadd_rn(__fmul_rn(__fadd_rn(y, 0.5f), bh1), a1);
    g_cx[1][n * HW + p] = __fadd_rn(__fmul_rn(__fadd_rn(x, 0.5f), bw2), b0);
    g_cy[1][n * HW + p] = __fadd_rn(__fmul_rn(__fadd_rn(y, 0.5f), bh2), b1);
    if (p == 0) {
        float d1 = __fsqrt_rn(__fadd_rn(__fmul_rn(bw1, bw1), __fmul_rn(bh1, bh1)));
        float d2 = __fsqrt_rn(__fadd_rn(__fmul_rn(bw2, bw2), __fmul_rn(bh2, bh2)));
        float md = fmaxf(d1, d2);
        uint32_t lo = 0u, hi = 0x7F7FFFFFu;   // [0, FLT_MAX]
        while (lo < hi) {
            uint32_t mid = lo + ((hi - lo) >> 1);
            float v = __uint_as_float(mid);
            if (__fdiv_rn(__fsqrt_rn(v), md) >= 16.0f) hi = mid;
            else lo = mid + 1;
        }
        g_dthr2[n] = __uint_as_float(lo);     // mask <=> d2 < g_dthr2[n]
    }
}

// Fused prep: transpose [c][p] -> [p][c], TF32-quantize into g_tf32, AND
// accumulate exact-fp32 column norms (stored as inverses) in the same pass.
// grid (32 ptiles, NB, 4), block 256. 32x32 smem tile.
__global__ __launch_bounds__(256) void prep_kernel(
    const float* __restrict__ p1, const float* __restrict__ p2,
    const float* __restrict__ z1, const float* __restrict__ z2) {
    int t = blockIdx.z;
    int n = blockIdx.y;
    int p0 = blockIdx.x * 32;
    const float* src = (t == 0) ? p1 : (t == 1) ? p2 : (t == 2) ? z1 : z2;
    src += (size_t)n * CDIM * HW;
    float* dst = g_tf32 + ((size_t)(t * NB + n) * HW) * CDIM;

    __shared__ float s[32][33];
    __shared__ float part[8][32];
    int tid = threadIdx.x;
    int rc = tid >> 5;        // 0..7
    int rp = tid & 31;        // 0..31
    float acc = 0.f;

#pragma unroll 1
    for (int ct = 0; ct < 8; ++ct) {
        int c0 = ct * 32;
#pragma unroll
        for (int j = 0; j < 4; ++j) {
            int c = rc + j * 8;
            s[c][rp] = src[(size_t)(c0 + c) * HW + p0 + rp];
        }
        __syncthreads();
#pragma unroll
        for (int i = 0; i < 4; ++i) {
            float v = s[rc * 4 + i][rp];
            acc += v * v;
        }
#pragma unroll
        for (int j = 0; j < 4; ++j) {
            int p = rc + j * 8;
            dst[(size_t)(p0 + p) * CDIM + c0 + rp] = tf32r(s[rp][p]);
        }
        __syncthreads();
    }
    part[rc][rp] = acc;
    __syncthreads();
    if (tid < 32) {
        float n2 = 0.f;
#pragma unroll
        for (int g = 0; g < 8; ++g) n2 += part[g][tid];
        g_ninv[t][n * HW + p0 + tid] = 1.0f / sqrtf(n2);
    }
}

// Fused TF32 tensor-core GEMM + cosine + mask + masked-mean reduction.
// 128(p) x 128(q) tile, BK=16, 3-stage cp.async ring (one barrier/stage),
// 8 warps (4M x 2N), warp tile 32x64 (mt=2, nt=8). 2 CTAs/SM.
// Mask = (d2 < T), T = exact monotone-equivalent threshold.
#define BM 128
#define BNQ 128
#define BK 16
#define NSTG 3
#define NT (CDIM / BK)    // 16 k-tiles
#define STAGE_A (BM * BK)              // floats
#define STAGE_B (BNQ * BK)             // floats
#define DYN_SMEM (NSTG * (STAGE_A + STAGE_B) * 4)   // 48 KB

__global__ __launch_bounds__(256, 2) void gemm_loss_kernel() {
    int z = blockIdx.z;          // 0..63 : (loss, n)
    int n = z & 31;
    int which = z >> 5;          // 0 -> (p1, z2), 1 -> (p2, z1)

    const float *Q, *K, *qiv, *kiv, *qcx, *qcy, *kcx, *kcy;
    if (which == 0) {
        Q = g_tf32 + ((size_t)(0 * NB + n) * HW) * CDIM;
        K = g_tf32 + ((size_t)(3 * NB + n) * HW) * CDIM;
        qiv = &g_ninv[0][n * HW]; kiv = &g_ninv[3][n * HW];
        qcx = &g_cx[0][n * HW]; qcy = &g_cy[0][n * HW];
        kcx = &g_cx[1][n * HW]; kcy = &g_cy[1][n * HW];
    } else {
        Q = g_tf32 + ((size_t)(1 * NB + n) * HW) * CDIM;
        K = g_tf32 + ((size_t)(2 * NB + n) * HW) * CDIM;
        qiv = &g_ninv[1][n * HW]; kiv = &g_ninv[2][n * HW];
        qcx = &g_cx[1][n * HW]; qcy = &g_cy[1][n * HW];
        kcx = &g_cx[0][n * HW]; kcy = &g_cy[0][n * HW];
    }
    float dthr2 = g_dthr2[n];

    extern __shared__ float dynsm[];
    float* Abase = dynsm;                         // NSTG stages of BM x BK
    float* Bbase = dynsm + NSTG * STAGE_A;        // NSTG stages of BNQ x BK
    __shared__ float warpS[8];
    __shared__ float warpC[8];

    int tid  = threadIdx.x;
    int lane = tid & 31;
    int warp = tid >> 5;          // 0..7
    int gid  = lane >> 2;         // 0..7
    int tig  = lane & 3;          // 0..3
    int warpM = warp >> 1;        // 0..3 -> 32-row band
    int warpN = warp & 1;         // 0..1 -> 64-col band
    int pBase = blockIdx.x * BM;
    int qBase = blockIdx.y * BNQ;

    // cp.async mapping: cr = row (0..63), co = float offset of 16B chunk
    int cr = tid >> 2;            // 0..63
    int co = (tid & 3) * 4;       // 0,4,8,12

    uint32_t sA = (uint32_t)__cvta_generic_to_shared(Abase);
    uint32_t sB = (uint32_t)__cvta_generic_to_shared(Bbase);
    const uint32_t aBuf = STAGE_A * 4;    // 8 KB
    const uint32_t bBuf = STAGE_B * 4;    // 8 KB
    uint32_t thOff = (uint32_t)((cr * BK + co) * 4);
    const float* qRow0 = Q + (size_t)(pBase + cr) * CDIM + co;
    const float* qRow1 = Q + (size_t)(pBase + cr + 64) * CDIM + co;
    const float* kRow0 = K + (size_t)(qBase + cr) * CDIM + co;
    const float* kRow1 = K + (size_t)(qBase + cr + 64) * CDIM + co;

    float d[2][8][4];
#pragma unroll
    for (int mt = 0; mt < 2; ++mt)
#pragma unroll
        for (int nt = 0; nt < 8; ++nt)
#pragma unroll
            for (int r = 0; r < 4; ++r) d[mt][nt][r] = 0.f;

    // prologue: issue stages 0 and 1 as separate groups
#pragma unroll
    for (int st = 0; st < 2; ++st) {
        CP_ASYNC16(sA + st * aBuf + thOff,                 qRow0 + st * BK);
        CP_ASYNC16(sA + st * aBuf + thOff + 64u * BK * 4u, qRow1 + st * BK);
        CP_ASYNC16(sB + st * bBuf + thOff,                 kRow0 + st * BK);
        CP_ASYNC16(sB + st * bBuf + thOff + 64u * BK * 4u, kRow1 + st * BK);
        CP_COMMIT();
    }

#pragma unroll
    for (int kt = 0; kt < NT; ++kt) {
        const int cur  = kt % NSTG;
        const int nxt2 = (kt + 2) % NSTG;
        if (kt < NT - 1) { CP_WAIT(1); } else { CP_WAIT(0); }
        __syncthreads();   // stage kt visible; fences reuse of buffer nxt2
        if (kt + 2 < NT) {
            CP_ASYNC16(sA + nxt2 * aBuf + thOff,                 qRow0 + (kt + 2) * BK);
            CP_ASYNC16(sA + nxt2 * aBuf + thOff + 64u * BK * 4u, qRow1 + (kt + 2) * BK);
            CP_ASYNC16(sB + nxt2 * bBuf + thOff,                 kRow0 + (kt + 2) * BK);
            CP_ASYNC16(sB + nxt2 * bBuf + thOff + 64u * BK * 4u, kRow1 + (kt + 2) * BK);
            CP_COMMIT();
        }
        // B fragments: one float4 per nt covers both k8 steps (8 loads/warp)
        const float* Bcur = Bbase + cur * STAGE_B;
        const float* Acur = Abase + cur * STAGE_A;
        float4 wb[8];
#pragma unroll
        for (int nt = 0; nt < 8; ++nt)
            wb[nt] = *(const float4*)(Bcur + (warpN * 64 + nt * 8 + gid) * BK + tig * 4);
#pragma unroll
        for (int mt = 0; mt < 2; ++mt) {
            int pm = warpM * 32 + mt * 16 + gid;
            float4 va = *(const float4*)(Acur + pm * BK + tig * 4);
            float4 vb = *(const float4*)(Acur + (pm + 8) * BK + tig * 4);
#pragma unroll
            for (int nt = 0; nt < 8; ++nt)
                mma_tf32(d[mt][nt], va.x, vb.x, va.y, vb.y, wb[nt].x, wb[nt].y);
#pragma unroll
            for (int nt = 0; nt < 8; ++nt)
                mma_tf32(d[mt][nt], va.z, vb.z, va.w, vb.w, wb[nt].z, wb[nt].w);
        }
    }

    // Epilogue: cos = sim * qinv * kinv; mask = (d2 < dthr2) (bit-exact).
    float qnv[2][2], qxv[2][2], qyv[2][2];
#pragma unroll
    for (int mt = 0; mt < 2; ++mt)
#pragma unroll
        for (int i2 = 0; i2 < 2; ++i2) {
            int p = pBase + warpM * 32 + mt * 16 + gid + i2 * 8;
            qnv[mt][i2] = qiv[p]; qxv[mt][i2] = qcx[p]; qyv[mt][i2] = qcy[p];
        }

    float lsum = 0.f, lcnt = 0.f;
#pragma unroll
    for (int nt = 0; nt < 8; ++nt) {
#pragma unroll
        for (int j2 = 0; j2 < 2; ++j2) {
            int q = qBase + warpN * 64 + nt * 8 + 2 * tig + j2;
            float kn = kiv[q], kx = kcx[q], ky = kcy[q];
#pragma unroll
            for (int mt = 0; mt < 2; ++mt) {
#pragma unroll
                for (int i2 = 0; i2 < 2; ++i2) {
                    float cosv = d[mt][nt][i2 * 2 + j2] * qnv[mt][i2] * kn;
                    float dx = __fsub_rn(qxv[mt][i2], kx);
                    float dy = __fsub_rn(qyv[mt][i2], ky);
                    float d2v = __fadd_rn(__fmul_rn(dx, dx), __fmul_rn(dy, dy));
                    if (d2v < dthr2) {
                        lsum += cosv;
                        lcnt += 1.0f;
                    }
                }
            }
        }
    }

    // warp-shuffle reduction, then one cross-warp pass, then fp64 atomics
#pragma unroll
    for (int sh = 16; sh > 0; sh >>= 1) {
        lsum += __shfl_xor_sync(0xFFFFFFFFu, lsum, sh);
        lcnt += __shfl_xor_sync(0xFFFFFFFFu, lcnt, sh);
    }
    if (lane == 0) { warpS[warp] = lsum; warpC[warp] = lcnt; }
    __syncthreads();
    if (warp == 0 && lane == 0) {
        float ts = 0.f, tc = 0.f;
#pragma unroll
        for (int w = 0; w < 8; ++w) { ts += warpS[w]; tc += warpC[w]; }
        atomicAdd(&g_sum[z], (double)ts);
        atomicAdd(&g_cnt[z], (double)tc);
    }
}

__global__ void final_kernel(float* __restrict__ out) {
    double l1 = 0.0, l2 = 0.0;
    for (int n = 0; n < 32; ++n) {
        l1 += g_sum[n]      / (g_cnt[n]      + 1e-6);
        l2 += g_sum[32 + n] / (g_cnt[32 + n] + 1e-6);
    }
    out[0] = (float)(-((l1 / 32.0) + (l2 / 32.0)) * 0.5);
}

// ---------------- launch ----------------
extern "C" void kernel_launch(void* const* d_in, const int* in_sizes, int n_in,
                              void* d_out, int out_size) {
    const float* p1 = (const float*)d_in[0];
    const float* p2 = (const float*)d_in[1];
    const float* z1 = (const float*)d_in[2];
    const float* z2 = (const float*)d_in[3];
    const float* c1 = (const float*)d_in[4];
    const float* c2 = (const float*)d_in[5];
    float* out = (float*)d_out;

    cudaFuncSetAttribute(gemm_loss_kernel,
                         cudaFuncAttributeMaxDynamicSharedMemorySize, DYN_SMEM);

    zero_kernel<<<1, 64>>>();
    centers_kernel<<<NB, 1024>>>(c1, c2);
    prep_kernel<<<dim3(32, NB, 4), 256>>>(p1, p2, z1, z2);
    gemm_loss_kernel<<<dim3(8, 8, 64), 256, DYN_SMEM>>>();
    final_kernel<<<1, 1>>>(out);
}